// round 11
// baseline (speedup 1.0000x reference)
#include <cuda_runtime.h>
#include <cstdint>
#include <math.h>

#define NV 8192
#define DV 256

// ---------------- device scratch (allocation-free rule) ----------------
__device__ float    g_Wht[NV * DV];     // Wh, tf32-rounded (B operand)
__device__ float    g_wa[DV];           // W @ a
__device__ float    g_u[NV];            // exp(f)
__device__ float    g_v[NV];            // exp(0.2 f)
__device__ float    g_c[NV];            // u/s
__device__ float    g_d[NV];            // v/s
__device__ unsigned g_bm[NV * 256];     // adjacency bitmask
__device__ float    g_part[2 * NV * DV];
__device__ float    g_elu_scratch[NV * DV];

__device__ __forceinline__ float elu_f(float x) { return x > 0.f ? x : expm1f(x); }
__device__ __forceinline__ uint32_t tf32r(float x) {
    uint32_t r; asm("cvt.rna.tf32.f32 %0, %1;" : "=r"(r) : "f"(x)); return r;
}
__device__ __forceinline__ void mma_tf32(float* d, const uint32_t* a, const uint32_t* b) {
    asm volatile("mma.sync.aligned.m16n8k8.row.col.f32.tf32.tf32.f32 "
        "{%0,%1,%2,%3},{%4,%5,%6,%7},{%8,%9},{%0,%1,%2,%3};"
        : "+f"(d[0]), "+f"(d[1]), "+f"(d[2]), "+f"(d[3])
        : "r"(a[0]), "r"(a[1]), "r"(a[2]), "r"(a[3]), "r"(b[0]), "r"(b[1]));
}
__device__ __forceinline__ uint32_t smem_u32(const void* p) {
    uint32_t a;
    asm("{ .reg .u64 t; cvta.to.shared.u64 t, %1; cvt.u32.u64 %0, t; }" : "=r"(a) : "l"(p));
    return a;
}
__device__ __forceinline__ void cp_async16(uint32_t dst, const void* src) {
    asm volatile("cp.async.ca.shared.global [%0], [%1], 16;" :: "r"(dst), "l"(src));
}
#define CP_COMMIT() asm volatile("cp.async.commit_group;" ::: "memory")
#define CP_WAIT0()  asm volatile("cp.async.wait_group 0;" ::: "memory")

// ---------------------------------------------------------------------------
// Kernel 1: Wh = h @ W via tf32 mma (also computes wa = W@a in block (0,0)).
// CTA = 128 rows x 128 cols (grid 64x2).
// ---------------------------------------------------------------------------
#define WH_SMEM (128 * 36 * 4 + 32 * 136 * 4)
__global__ __launch_bounds__(512) void k_wh_mma(const float* __restrict__ h,
                                                const float* __restrict__ W,
                                                const float* __restrict__ a) {
    extern __shared__ char sm[];
    uint32_t* sA = (uint32_t*)sm;
    float*    sB = (float*)(sm + 128 * 36 * 4);
    const int tid = threadIdx.x;
    const int wid = tid >> 5, lane = tid & 31;
    const int wm = wid >> 2, wn = wid & 3;
    const int r0 = blockIdx.x * 128;
    const int cb = blockIdx.y * 128;
    const int br = tid >> 2, kq = (tid & 3) * 8;

    if (blockIdx.x == 0 && blockIdx.y == 0 && tid < 256) {
        const float4* W4 = (const float4*)W;
        const float4* a4 = (const float4*)a;
        float s = 0.f;
#pragma unroll 8
        for (int j = 0; j < 64; j++) {
            float4 w = __ldg(&W4[tid * 64 + j]);
            float4 av = __ldg(&a4[j]);
            s += w.x * av.x + w.y * av.y + w.z * av.z + w.w * av.w;
        }
        g_wa[tid] = s;
    }

    float acc[2][4][4];
#pragma unroll
    for (int mt = 0; mt < 2; mt++)
#pragma unroll
        for (int nb = 0; nb < 4; nb++)
#pragma unroll
            for (int q = 0; q < 4; q++) acc[mt][nb][q] = 0.f;

    for (int c = 0; c < 8; c++) {
        const int kb = c * 32;
        {
            float4 h0 = __ldg((const float4*)&h[(size_t)(r0 + br) * DV + kb + kq]);
            float4 h1 = __ldg((const float4*)&h[(size_t)(r0 + br) * DV + kb + kq + 4]);
            *(uint4*)&sA[br * 36 + kq]     = make_uint4(tf32r(h0.x), tf32r(h0.y), tf32r(h0.z), tf32r(h0.w));
            *(uint4*)&sA[br * 36 + kq + 4] = make_uint4(tf32r(h1.x), tf32r(h1.y), tf32r(h1.z), tf32r(h1.w));
        }
#pragma unroll
        for (int q = 0; q < 2; q++) {
            int idx = q * 512 + tid;
            int row = idx >> 5, col = (idx & 31) << 2;
            float4 w = __ldg((const float4*)&W[(size_t)(kb + row) * DV + cb + col]);
            float4 t;
            t.x = __uint_as_float(tf32r(w.x)); t.y = __uint_as_float(tf32r(w.y));
            t.z = __uint_as_float(tf32r(w.z)); t.w = __uint_as_float(tf32r(w.w));
            *(float4*)&sB[row * 136 + col] = t;
        }
        __syncthreads();
#pragma unroll
        for (int kk = 0; kk < 4; kk++) {
            uint32_t afr[2][4];
#pragma unroll
            for (int mt = 0; mt < 2; mt++) {
                int r = wm * 32 + mt * 16 + (lane >> 2);
                int cc = kk * 8 + (lane & 3);
                afr[mt][0] = sA[r * 36 + cc];
                afr[mt][1] = sA[(r + 8) * 36 + cc];
                afr[mt][2] = sA[r * 36 + cc + 4];
                afr[mt][3] = sA[(r + 8) * 36 + cc + 4];
            }
#pragma unroll
            for (int nb = 0; nb < 4; nb++) {
                uint32_t bfr[2];
                int kr = kk * 8 + (lane & 3);
                int nc = wn * 32 + nb * 8 + (lane >> 2);
                bfr[0] = __float_as_uint(sB[kr * 136 + nc]);
                bfr[1] = __float_as_uint(sB[(kr + 4) * 136 + nc]);
                mma_tf32(acc[0][nb], afr[0], bfr);
                mma_tf32(acc[1][nb], afr[1], bfr);
            }
        }
        __syncthreads();
    }
#pragma unroll
    for (int mt = 0; mt < 2; mt++)
#pragma unroll
        for (int nb = 0; nb < 4; nb++) {
            int gr = r0 + wm * 32 + mt * 16 + (lane >> 2);
            int cl = cb + wn * 32 + nb * 8 + (lane & 3) * 2;
            float* base = &g_Wht[(size_t)gr * DV + cl];
            base[0] = __uint_as_float(tf32r(acc[mt][nb][0]));
            base[1] = __uint_as_float(tf32r(acc[mt][nb][1]));
            base[8 * DV]     = __uint_as_float(tf32r(acc[mt][nb][2]));
            base[8 * DV + 1] = __uint_as_float(tf32r(acc[mt][nb][3]));
        }
}

// ---------------------------------------------------------------------------
// Kernel 2: f = h @ wa (exact); u = exp(f), v = exp(0.2 f)
// ---------------------------------------------------------------------------
__global__ __launch_bounds__(256) void k_f(const float* __restrict__ h) {
    const int wid = threadIdx.x >> 5, lane = threadIdx.x & 31;
    const int row = blockIdx.x * 8 + wid;
    float s = 0.f;
#pragma unroll
    for (int i = 0; i < 2; i++) {
        float4 w = __ldg((const float4*)&h[(size_t)row * DV + lane * 8 + i * 4]);
        float4 av = __ldg((const float4*)&g_wa[lane * 8 + i * 4]);
        s += w.x * av.x + w.y * av.y + w.z * av.z + w.w * av.w;
    }
#pragma unroll
    for (int m = 16; m; m >>= 1) s += __shfl_xor_sync(0xffffffffu, s, m);
    if (lane == 0) {
        g_u[row] = __expf(s);
        g_v[row] = __expf(0.2f * s);
    }
}

// ---------------------------------------------------------------------------
// Kernel 3: bitmask + rowsum (separable). One block per row.
// ---------------------------------------------------------------------------
__global__ __launch_bounds__(256) void k_prep(const int* __restrict__ adj) {
    const int row = blockIdx.x;
    const int wid = threadIdx.x >> 5, lane = threadIdx.x & 31;
    const float ui = __ldg(&g_u[row]);
    const float vi = __ldg(&g_v[row]);
    const float th = 1.f / ui;
    const int4* ar = (const int4*)(adj + (size_t)row * NV);
    const float4* u4p = (const float4*)g_u;
    const float4* v4p = (const float4*)g_v;

    float su = 0.f, sv = 0.f;
#pragma unroll
    for (int it = 0; it < 8; it++) {
        int idx4 = wid * 256 + it * 32 + lane;
        int4   ad = __ldg(&ar[idx4]);
        float4 u4 = __ldg(&u4p[idx4]);
        float4 v4 = __ldg(&v4p[idx4]);
        bool m0 = ad.x > 0, m1 = ad.y > 0, m2 = ad.z > 0, m3 = ad.w > 0;
        uint32_t nib = (m0 ? 1u : 0u) | (m1 ? 2u : 0u) | (m2 ? 4u : 0u) | (m3 ? 8u : 0u);
        bool p0 = u4.x > th, p1 = u4.y > th, p2 = u4.z > th, p3 = u4.w > th;
        su += (m0 && p0) ? u4.x : 0.f;  sv += (m0 && !p0) ? v4.x : 0.f;
        su += (m1 && p1) ? u4.y : 0.f;  sv += (m1 && !p1) ? v4.y : 0.f;
        su += (m2 && p2) ? u4.z : 0.f;  sv += (m2 && !p2) ? v4.z : 0.f;
        su += (m3 && p3) ? u4.w : 0.f;  sv += (m3 && !p3) ? v4.w : 0.f;
        uint32_t o = __shfl_xor_sync(0xffffffffu, nib, 1);
        uint32_t byt = (lane & 1) ? (o | (nib << 4)) : (nib | (o << 4));
        o = __shfl_xor_sync(0xffffffffu, byt, 2);
        uint32_t hlf = (lane & 2) ? (o | (byt << 8)) : (byt | (o << 8));
        o = __shfl_xor_sync(0xffffffffu, hlf, 4);
        uint32_t wrd = (lane & 4) ? (o | (hlf << 16)) : (hlf | (o << 16));
        if ((lane & 7) == 0)
            g_bm[(size_t)row * 256 + wid * 32 + it * 4 + (lane >> 3)] = wrd;
    }
#pragma unroll
    for (int m = 16; m; m >>= 1) {
        su += __shfl_xor_sync(0xffffffffu, su, m);
        sv += __shfl_xor_sync(0xffffffffu, sv, m);
    }
    __shared__ float ssu[8], ssv[8];
    if (lane == 0) { ssu[wid] = su; ssv[wid] = sv; }
    __syncthreads();
    if (threadIdx.x == 0) {
        float tu = 0.f, tv = 0.f;
#pragma unroll
        for (int i = 0; i < 8; i++) { tu += ssu[i]; tv += ssv[i]; }
        float s = ui * tu + vi * tv;
        g_c[row] = ui / s;
        g_d[row] = vi / s;
    }
}

// ---------------------------------------------------------------------------
// Kernel 4: h' = alpha @ Wh. 256 threads, 8 warps (2x4), warp tile 32x64,
// CTA 64 x 256, split-K=2 -> 256 CTAs, 2 CTAs/SM (independent barrier
// domains hide each other's build/sync latency). u/v via __ldg (L2).
// B: 2-stage cp.async ring, XOR swizzle. bm word prefetched 1 chunk ahead.
// ---------------------------------------------------------------------------
#define AT_A   0                               // 2 x 64*36*4  = 18432
#define AT_B   (2 * 9216)                      // 2 x 32*256*4 = 65536
#define AT_SC  (AT_B + 2 * 32768)
#define AT_SMEM (AT_SC + 3 * 64 * 4)           // 84736 B -> 2 CTAs/SM

__global__ __launch_bounds__(256, 2) void k_attn(float* __restrict__ out_alpha) {
    extern __shared__ char sm[];
    uint32_t* sAs[2] = { (uint32_t*)(sm + AT_A), (uint32_t*)(sm + AT_A + 9216) };
    float* sc  = (float*)(sm + AT_SC);
    float* sd  = sc + 64;
    float* stt = sd + 64;

    const int tid = threadIdx.x;
    const int wid = tid >> 5, lane = tid & 31;
    const int wm = wid >> 2, wn = wid & 3;        // 2 x 4 warps, tile 32x64
    const int kh = blockIdx.x, rt = blockIdx.y;
    const int r0 = rt * 64;
    const int br = tid >> 2, kq0 = (tid & 3) * 8; // A-build: 8 els/thread
    const bool wA = (out_alpha != nullptr);
    const uint32_t sbB = smem_u32(sm + AT_B);
    const size_t bmBase = (size_t)(r0 + br) * 256 + (size_t)kh * 128;

    if (tid < 64) {
        sc[tid]  = g_c[r0 + tid];
        sd[tid]  = g_d[r0 + tid];
        stt[tid] = 1.f / g_u[r0 + tid];
    }

    float acc[2][8][4];
#pragma unroll
    for (int mt = 0; mt < 2; mt++)
#pragma unroll
        for (int nb = 0; nb < 8; nb++)
#pragma unroll
            for (int q = 0; q < 4; q++) acc[mt][nb][q] = 0.f;
    __syncthreads();

    // B copy with XOR swizzle: (row,col) -> word row*256 + (col ^ ((row&3)<<3))
    auto cp_B = [&](int c, int s) {
        const int kb = kh * (NV / 2) + c * 32;
        uint32_t base = sbB + s * 32768;
#pragma unroll
        for (int q = 0; q < 8; q++) {
            int idx = q * 256 + tid;
            int row = idx >> 6, col4 = (idx & 63) << 2;
            int sw = col4 ^ ((row & 3) << 3);
            cp_async16(base + (row * 256 + sw) * 4,
                       &g_Wht[(size_t)(kb + row) * DV + col4]);
        }
    };
    auto build_A = [&](int c, int s, uint32_t word) {
        const int kb = kh * (NV / 2) + c * 32;
        float ci = sc[br], di = sd[br], th = stt[br];
        uint32_t* sA = sAs[s];
#pragma unroll
        for (int g4 = 0; g4 < 2; g4++) {
            int j = kq0 + g4 * 4;
            float4 u4 = __ldg((const float4*)&g_u[kb + j]);
            float4 v4 = __ldg((const float4*)&g_v[kb + j]);
            const float ue[4] = {u4.x, u4.y, u4.z, u4.w};
            const float ve[4] = {v4.x, v4.y, v4.z, v4.w};
            float av[4];
#pragma unroll
            for (int e = 0; e < 4; e++) {
                bool bit = (word >> (j + e)) & 1u;
                av[e] = bit ? ((ue[e] > th) ? ci * ue[e] : di * ve[e]) : 0.f;
            }
            if (wA)
                *(float4*)&out_alpha[(size_t)(r0 + br) * NV + kb + j] =
                    make_float4(av[0], av[1], av[2], av[3]);
            *(uint4*)&sA[br * 36 + j] =
                make_uint4(tf32r(av[0]), tf32r(av[1]), tf32r(av[2]), tf32r(av[3]));
        }
    };
    const int xr = (lane & 3) << 3;               // B read swizzle per lane
    auto do_mma = [&](int sa, int sb) {
        uint32_t* sA = sAs[sa];
        const float* sB = (const float*)(sm + AT_B + sb * 32768);
#pragma unroll
        for (int kk = 0; kk < 4; kk++) {
            uint32_t afr[2][4];
#pragma unroll
            for (int mt = 0; mt < 2; mt++) {
                int r = wm * 32 + mt * 16 + (lane >> 2);
                int cc = kk * 8 + (lane & 3);
                afr[mt][0] = sA[r * 36 + cc];
                afr[mt][1] = sA[(r + 8) * 36 + cc];
                afr[mt][2] = sA[r * 36 + cc + 4];
                afr[mt][3] = sA[(r + 8) * 36 + cc + 4];
            }
            int kr = kk * 8 + (lane & 3);
#pragma unroll
            for (int nb = 0; nb < 8; nb++) {
                int nc = wn * 64 + nb * 8 + (lane >> 2);
                int ncx = nc ^ xr;
                uint32_t bfr[2];
                bfr[0] = __float_as_uint(sB[kr * 256 + ncx]);
                bfr[1] = __float_as_uint(sB[(kr + 4) * 256 + ncx]);
                mma_tf32(acc[0][nb], afr[0], bfr);
                mma_tf32(acc[1][nb], afr[1], bfr);
            }
        }
    };

    // ---- prologue ----
    uint32_t wcur = __ldg(&g_bm[bmBase + 0]);
    cp_B(0, 0); CP_COMMIT();
    build_A(0, 0, wcur);
    wcur = __ldg(&g_bm[bmBase + 1]);
    CP_WAIT0();
    __syncthreads();

#pragma unroll 1
    for (int c = 0; c < 128; c++) {
        uint32_t wpre = 0;
        if (c + 2 < 128) wpre = __ldg(&g_bm[bmBase + c + 2]);
        if (c + 1 < 128) cp_B(c + 1, (c + 1) & 1);
        CP_COMMIT();
        do_mma(c & 1, c & 1);
        if (c + 1 < 128) build_A(c + 1, (c + 1) & 1, wcur);
        wcur = wpre;
        CP_WAIT0();
        __syncthreads();
    }

    // ---- epilogue: split-K partials ----
#pragma unroll
    for (int mt = 0; mt < 2; mt++)
#pragma unroll
        for (int nb = 0; nb < 8; nb++) {
            int gr = r0 + wm * 32 + mt * 16 + (lane >> 2);
            int cl = wn * 64 + nb * 8 + (lane & 3) * 2;
            float* base = &g_part[((size_t)kh * NV + gr) * DV + cl];
            *(float2*)base            = make_float2(acc[mt][nb][0], acc[mt][nb][1]);
            *(float2*)(base + 8 * DV) = make_float2(acc[mt][nb][2], acc[mt][nb][3]);
        }
}

// ---------------------------------------------------------------------------
// Kernel 5: combine split-K partials + elu
// ---------------------------------------------------------------------------
__global__ __launch_bounds__(256) void k_combine(float* __restrict__ out_elu) {
    float* o = out_elu ? out_elu : g_elu_scratch;
    size_t i = ((size_t)blockIdx.x * 256 + threadIdx.x) * 4;
    float4 p0 = *(float4*)&g_part[i];
    float4 p1 = *(float4*)&g_part[(size_t)NV * DV + i];
    float4 r;
    r.x = elu_f(p0.x + p1.x);
    r.y = elu_f(p0.y + p1.y);
    r.z = elu_f(p0.z + p1.z);
    r.w = elu_f(p0.w + p1.w);
    *(float4*)&o[i] = r;
}

// ---------------------------------------------------------------------------
extern "C" void kernel_launch(void* const* d_in, const int* in_sizes, int n_in,
                              void* d_out, int out_size) {
    const float* h   = (const float*)d_in[0];
    const int*   adj = (const int*)d_in[1];
    const float* W   = (const float*)d_in[2];
    const float* a   = (const float*)d_in[3];
    float* out = (float*)d_out;

    const long long elu_n = (long long)NV * DV;
    const long long alp_n = (long long)NV * NV;
    float* out_elu;
    float* out_alpha;
    if ((long long)out_size >= elu_n + alp_n) { out_elu = out; out_alpha = out + elu_n; }
    else if ((long long)out_size == alp_n)    { out_elu = nullptr; out_alpha = out; }
    else                                      { out_elu = out; out_alpha = nullptr; }

    cudaFuncSetAttribute(k_wh_mma, cudaFuncAttributeMaxDynamicSharedMemorySize, WH_SMEM);
    cudaFuncSetAttribute(k_attn,   cudaFuncAttributeMaxDynamicSharedMemorySize, AT_SMEM);

    dim3 gW(NV / 128, 2);
    k_wh_mma<<<gW, 512, WH_SMEM>>>(h, W, a);
    k_f<<<NV / 8, 256>>>(h);
    k_prep<<<NV, 256>>>(adj);
    dim3 gA(2, NV / 64);
    k_attn<<<gA, 256, AT_SMEM>>>(out_alpha);
    k_combine<<<(unsigned)(elu_n / 4 / 256), 256>>>(out_elu);
}

// round 12
// speedup vs baseline: 1.2792x; 1.2792x over previous
#include <cuda_runtime.h>
#include <cstdint>
#include <math.h>

#define NV 8192
#define DV 256

// ---------------- device scratch (allocation-free rule) ----------------
__device__ float    g_Wht[NV * DV];     // Wh, tf32-rounded (B operand)
__device__ float    g_wa[DV];           // W @ a
__device__ float    g_u[NV];            // exp(f)
__device__ float    g_v[NV];            // exp(0.2 f)
__device__ float    g_c[NV];            // u/s
__device__ float    g_d[NV];            // v/s
__device__ unsigned g_bm[NV * 256];     // adjacency bitmask
__device__ float    g_part[2 * NV * DV];
__device__ float    g_elu_scratch[NV * DV];

__device__ __forceinline__ float elu_f(float x) { return x > 0.f ? x : expm1f(x); }
__device__ __forceinline__ uint32_t tf32r(float x) {
    uint32_t r; asm("cvt.rna.tf32.f32 %0, %1;" : "=r"(r) : "f"(x)); return r;
}
__device__ __forceinline__ void mma_tf32(float* d, const uint32_t* a, const uint32_t* b) {
    asm volatile("mma.sync.aligned.m16n8k8.row.col.f32.tf32.tf32.f32 "
        "{%0,%1,%2,%3},{%4,%5,%6,%7},{%8,%9},{%0,%1,%2,%3};"
        : "+f"(d[0]), "+f"(d[1]), "+f"(d[2]), "+f"(d[3])
        : "r"(a[0]), "r"(a[1]), "r"(a[2]), "r"(a[3]), "r"(b[0]), "r"(b[1]));
}
__device__ __forceinline__ uint32_t smem_u32(const void* p) {
    uint32_t a;
    asm("{ .reg .u64 t; cvta.to.shared.u64 t, %1; cvt.u32.u64 %0, t; }" : "=r"(a) : "l"(p));
    return a;
}
__device__ __forceinline__ void cp_async16(uint32_t dst, const void* src) {
    asm volatile("cp.async.ca.shared.global [%0], [%1], 16;" :: "r"(dst), "l"(src));
}
#define CP_COMMIT() asm volatile("cp.async.commit_group;" ::: "memory")
#define CP_WAIT0()  asm volatile("cp.async.wait_group 0;" ::: "memory")

// ---------------------------------------------------------------------------
// Kernel 1: Wh = h @ W via tf32 mma (also computes wa = W@a in block (0,0)).
// CTA = 128 rows x 128 cols (grid 64x2).
// ---------------------------------------------------------------------------
#define WH_SMEM (128 * 36 * 4 + 32 * 136 * 4)
__global__ __launch_bounds__(512) void k_wh_mma(const float* __restrict__ h,
                                                const float* __restrict__ W,
                                                const float* __restrict__ a) {
    extern __shared__ char sm[];
    uint32_t* sA = (uint32_t*)sm;
    float*    sB = (float*)(sm + 128 * 36 * 4);
    const int tid = threadIdx.x;
    const int wid = tid >> 5, lane = tid & 31;
    const int wm = wid >> 2, wn = wid & 3;
    const int r0 = blockIdx.x * 128;
    const int cb = blockIdx.y * 128;
    const int br = tid >> 2, kq = (tid & 3) * 8;

    if (blockIdx.x == 0 && blockIdx.y == 0 && tid < 256) {
        const float4* W4 = (const float4*)W;
        const float4* a4 = (const float4*)a;
        float s = 0.f;
#pragma unroll 8
        for (int j = 0; j < 64; j++) {
            float4 w = __ldg(&W4[tid * 64 + j]);
            float4 av = __ldg(&a4[j]);
            s += w.x * av.x + w.y * av.y + w.z * av.z + w.w * av.w;
        }
        g_wa[tid] = s;
    }

    float acc[2][4][4];
#pragma unroll
    for (int mt = 0; mt < 2; mt++)
#pragma unroll
        for (int nb = 0; nb < 4; nb++)
#pragma unroll
            for (int q = 0; q < 4; q++) acc[mt][nb][q] = 0.f;

    for (int c = 0; c < 8; c++) {
        const int kb = c * 32;
        {
            float4 h0 = __ldg((const float4*)&h[(size_t)(r0 + br) * DV + kb + kq]);
            float4 h1 = __ldg((const float4*)&h[(size_t)(r0 + br) * DV + kb + kq + 4]);
            *(uint4*)&sA[br * 36 + kq]     = make_uint4(tf32r(h0.x), tf32r(h0.y), tf32r(h0.z), tf32r(h0.w));
            *(uint4*)&sA[br * 36 + kq + 4] = make_uint4(tf32r(h1.x), tf32r(h1.y), tf32r(h1.z), tf32r(h1.w));
        }
#pragma unroll
        for (int q = 0; q < 2; q++) {
            int idx = q * 512 + tid;
            int row = idx >> 5, col = (idx & 31) << 2;
            float4 w = __ldg((const float4*)&W[(size_t)(kb + row) * DV + cb + col]);
            float4 t;
            t.x = __uint_as_float(tf32r(w.x)); t.y = __uint_as_float(tf32r(w.y));
            t.z = __uint_as_float(tf32r(w.z)); t.w = __uint_as_float(tf32r(w.w));
            *(float4*)&sB[row * 136 + col] = t;
        }
        __syncthreads();
#pragma unroll
        for (int kk = 0; kk < 4; kk++) {
            uint32_t afr[2][4];
#pragma unroll
            for (int mt = 0; mt < 2; mt++) {
                int r = wm * 32 + mt * 16 + (lane >> 2);
                int cc = kk * 8 + (lane & 3);
                afr[mt][0] = sA[r * 36 + cc];
                afr[mt][1] = sA[(r + 8) * 36 + cc];
                afr[mt][2] = sA[r * 36 + cc + 4];
                afr[mt][3] = sA[(r + 8) * 36 + cc + 4];
            }
#pragma unroll
            for (int nb = 0; nb < 4; nb++) {
                uint32_t bfr[2];
                int kr = kk * 8 + (lane & 3);
                int nc = wn * 32 + nb * 8 + (lane >> 2);
                bfr[0] = __float_as_uint(sB[kr * 136 + nc]);
                bfr[1] = __float_as_uint(sB[(kr + 4) * 136 + nc]);
                mma_tf32(acc[0][nb], afr[0], bfr);
                mma_tf32(acc[1][nb], afr[1], bfr);
            }
        }
        __syncthreads();
    }
#pragma unroll
    for (int mt = 0; mt < 2; mt++)
#pragma unroll
        for (int nb = 0; nb < 4; nb++) {
            int gr = r0 + wm * 32 + mt * 16 + (lane >> 2);
            int cl = cb + wn * 32 + nb * 8 + (lane & 3) * 2;
            float* base = &g_Wht[(size_t)gr * DV + cl];
            base[0] = __uint_as_float(tf32r(acc[mt][nb][0]));
            base[1] = __uint_as_float(tf32r(acc[mt][nb][1]));
            base[8 * DV]     = __uint_as_float(tf32r(acc[mt][nb][2]));
            base[8 * DV + 1] = __uint_as_float(tf32r(acc[mt][nb][3]));
        }
}

// ---------------------------------------------------------------------------
// Kernel 2: f = h @ wa (exact); u = exp(f), v = exp(0.2 f)
// ---------------------------------------------------------------------------
__global__ __launch_bounds__(256) void k_f(const float* __restrict__ h) {
    const int wid = threadIdx.x >> 5, lane = threadIdx.x & 31;
    const int row = blockIdx.x * 8 + wid;
    float s = 0.f;
#pragma unroll
    for (int i = 0; i < 2; i++) {
        float4 w = __ldg((const float4*)&h[(size_t)row * DV + lane * 8 + i * 4]);
        float4 av = __ldg((const float4*)&g_wa[lane * 8 + i * 4]);
        s += w.x * av.x + w.y * av.y + w.z * av.z + w.w * av.w;
    }
#pragma unroll
    for (int m = 16; m; m >>= 1) s += __shfl_xor_sync(0xffffffffu, s, m);
    if (lane == 0) {
        g_u[row] = __expf(s);
        g_v[row] = __expf(0.2f * s);
    }
}

// ---------------------------------------------------------------------------
// Kernel 3: bitmask + rowsum (separable). One block per row.
// ---------------------------------------------------------------------------
__global__ __launch_bounds__(256) void k_prep(const int* __restrict__ adj) {
    const int row = blockIdx.x;
    const int wid = threadIdx.x >> 5, lane = threadIdx.x & 31;
    const float ui = __ldg(&g_u[row]);
    const float vi = __ldg(&g_v[row]);
    const float th = 1.f / ui;
    const int4* ar = (const int4*)(adj + (size_t)row * NV);
    const float4* u4p = (const float4*)g_u;
    const float4* v4p = (const float4*)g_v;

    float su = 0.f, sv = 0.f;
#pragma unroll
    for (int it = 0; it < 8; it++) {
        int idx4 = wid * 256 + it * 32 + lane;
        int4   ad = __ldg(&ar[idx4]);
        float4 u4 = __ldg(&u4p[idx4]);
        float4 v4 = __ldg(&v4p[idx4]);
        bool m0 = ad.x > 0, m1 = ad.y > 0, m2 = ad.z > 0, m3 = ad.w > 0;
        uint32_t nib = (m0 ? 1u : 0u) | (m1 ? 2u : 0u) | (m2 ? 4u : 0u) | (m3 ? 8u : 0u);
        bool p0 = u4.x > th, p1 = u4.y > th, p2 = u4.z > th, p3 = u4.w > th;
        su += (m0 && p0) ? u4.x : 0.f;  sv += (m0 && !p0) ? v4.x : 0.f;
        su += (m1 && p1) ? u4.y : 0.f;  sv += (m1 && !p1) ? v4.y : 0.f;
        su += (m2 && p2) ? u4.z : 0.f;  sv += (m2 && !p2) ? v4.z : 0.f;
        su += (m3 && p3) ? u4.w : 0.f;  sv += (m3 && !p3) ? v4.w : 0.f;
        uint32_t o = __shfl_xor_sync(0xffffffffu, nib, 1);
        uint32_t byt = (lane & 1) ? (o | (nib << 4)) : (nib | (o << 4));
        o = __shfl_xor_sync(0xffffffffu, byt, 2);
        uint32_t hlf = (lane & 2) ? (o | (byt << 8)) : (byt | (o << 8));
        o = __shfl_xor_sync(0xffffffffu, hlf, 4);
        uint32_t wrd = (lane & 4) ? (o | (hlf << 16)) : (hlf | (o << 16));
        if ((lane & 7) == 0)
            g_bm[(size_t)row * 256 + wid * 32 + it * 4 + (lane >> 3)] = wrd;
    }
#pragma unroll
    for (int m = 16; m; m >>= 1) {
        su += __shfl_xor_sync(0xffffffffu, su, m);
        sv += __shfl_xor_sync(0xffffffffu, sv, m);
    }
    __shared__ float ssu[8], ssv[8];
    if (lane == 0) { ssu[wid] = su; ssv[wid] = sv; }
    __syncthreads();
    if (threadIdx.x == 0) {
        float tu = 0.f, tv = 0.f;
#pragma unroll
        for (int i = 0; i < 8; i++) { tu += ssu[i]; tv += ssv[i]; }
        float s = ui * tu + vi * tv;
        g_c[row] = ui / s;
        g_d[row] = vi / s;
    }
}

// ---------------------------------------------------------------------------
// Kernel 4: h' = alpha @ Wh. CTA = 128 rows x 128 cols, 256 threads
// (8 warps = 4 wm x 2 wn, warp tile 32x64, acc=64). 2 CTAs/SM.
// grid (4, 64): x = kh + 2*cb  -> co-resident pairs are (kh=0, kh=1) of the
// SAME rows/cols: independent barrier domains overlap build/sync vs HMMA,
// with zero added traffic (work fully disjoint in k).
// ---------------------------------------------------------------------------
#define AT_A   0                               // 2 x 128*36*4 = 36864
#define AT_B   (2 * 18432)                     // 2 x 32*128*4 = 32768
#define AT_SC  (AT_B + 2 * 16384)
#define AT_SMEM (AT_SC + 3 * 128 * 4)          // 71168 B -> 2 CTAs/SM

__global__ __launch_bounds__(256, 2) void k_attn(float* __restrict__ out_alpha) {
    extern __shared__ char sm[];
    uint32_t* sAs[2] = { (uint32_t*)(sm + AT_A), (uint32_t*)(sm + AT_A + 18432) };
    float* sc  = (float*)(sm + AT_SC);
    float* sd  = sc + 128;
    float* stt = sd + 128;

    const int tid = threadIdx.x;
    const int wid = tid >> 5, lane = tid & 31;
    const int wm = wid >> 1, wn = wid & 1;        // 4 x 2 warps, tile 32x64
    const int kh = blockIdx.x & 1, cb = blockIdx.x >> 1;
    const int r0 = blockIdx.y * 128;
    const int c0 = cb * 128;
    const int br = tid >> 1, kq0 = (tid & 1) * 16; // A-build: 16 els/thread
    const bool wA = (out_alpha != nullptr) && (cb == 0);
    const uint32_t sbB = smem_u32(sm + AT_B);
    const size_t bmBase = (size_t)(r0 + br) * 256 + (size_t)kh * 128;

    if (tid < 128) {
        sc[tid]  = g_c[r0 + tid];
        sd[tid]  = g_d[r0 + tid];
        stt[tid] = 1.f / g_u[r0 + tid];
    }

    float acc[2][8][4];
#pragma unroll
    for (int mt = 0; mt < 2; mt++)
#pragma unroll
        for (int nb = 0; nb < 8; nb++)
#pragma unroll
            for (int q = 0; q < 4; q++) acc[mt][nb][q] = 0.f;
    __syncthreads();

    // B copy, XOR swizzle: (row,col) -> word row*128 + (col ^ ((row&3)<<3))
    auto cp_B = [&](int c, int s) {
        const int kb = kh * (NV / 2) + c * 32;
        uint32_t base = sbB + s * 16384;
#pragma unroll
        for (int q = 0; q < 4; q++) {
            int idx = q * 256 + tid;
            int row = idx >> 5, col4 = (idx & 31) << 2;
            int sw = col4 ^ ((row & 3) << 3);
            cp_async16(base + (row * 128 + sw) * 4,
                       &g_Wht[(size_t)(kb + row) * DV + c0 + col4]);
        }
    };
    auto build_A = [&](int c, int s, uint32_t word) {
        const int kb = kh * (NV / 2) + c * 32;
        float ci = sc[br], di = sd[br], th = stt[br];
        uint32_t* sA = sAs[s];
#pragma unroll
        for (int g4 = 0; g4 < 4; g4++) {
            int j = kq0 + g4 * 4;
            float4 u4 = __ldg((const float4*)&g_u[kb + j]);
            float4 v4 = __ldg((const float4*)&g_v[kb + j]);
            const float ue[4] = {u4.x, u4.y, u4.z, u4.w};
            const float ve[4] = {v4.x, v4.y, v4.z, v4.w};
            float av[4];
#pragma unroll
            for (int e = 0; e < 4; e++) {
                bool bit = (word >> (j + e)) & 1u;
                av[e] = bit ? ((ue[e] > th) ? ci * ue[e] : di * ve[e]) : 0.f;
            }
            if (wA)
                *(float4*)&out_alpha[(size_t)(r0 + br) * NV + kb + j] =
                    make_float4(av[0], av[1], av[2], av[3]);
            *(uint4*)&sAs[s][br * 36 + j] =
                make_uint4(tf32r(av[0]), tf32r(av[1]), tf32r(av[2]), tf32r(av[3]));
        }
    };
    const int xr = (lane & 3) << 3;               // B read swizzle per lane
    auto do_mma = [&](int s) {
        uint32_t* sA = sAs[s];
        const float* sB = (const float*)(sm + AT_B + s * 16384);
#pragma unroll
        for (int kk = 0; kk < 4; kk++) {
            uint32_t afr[2][4];
#pragma unroll
            for (int mt = 0; mt < 2; mt++) {
                int r = wm * 32 + mt * 16 + (lane >> 2);
                int cc = kk * 8 + (lane & 3);
                afr[mt][0] = sA[r * 36 + cc];
                afr[mt][1] = sA[(r + 8) * 36 + cc];
                afr[mt][2] = sA[r * 36 + cc + 4];
                afr[mt][3] = sA[(r + 8) * 36 + cc + 4];
            }
            int kr = kk * 8 + (lane & 3);
#pragma unroll
            for (int nb = 0; nb < 8; nb++) {
                int nc = wn * 64 + nb * 8 + (lane >> 2);
                int ncx = nc ^ xr;
                uint32_t bfr[2];
                bfr[0] = __float_as_uint(sB[kr * 128 + ncx]);
                bfr[1] = __float_as_uint(sB[(kr + 4) * 128 + ncx]);
                mma_tf32(acc[0][nb], afr[0], bfr);
                mma_tf32(acc[1][nb], afr[1], bfr);
            }
        }
    };

    // ---- prologue ----
    uint32_t wcur = __ldg(&g_bm[bmBase + 0]);
    cp_B(0, 0); CP_COMMIT();
    build_A(0, 0, wcur);
    wcur = __ldg(&g_bm[bmBase + 1]);
    CP_WAIT0();
    __syncthreads();

#pragma unroll 1
    for (int c = 0; c < 128; c++) {
        uint32_t wpre = 0;
        if (c + 2 < 128) wpre = __ldg(&g_bm[bmBase + c + 2]);
        if (c + 1 < 128) cp_B(c + 1, (c + 1) & 1);
        CP_COMMIT();
        do_mma(c & 1);
        if (c + 1 < 128) build_A(c + 1, (c + 1) & 1, wcur);
        wcur = wpre;
        CP_WAIT0();
        __syncthreads();
    }

    // ---- epilogue: split-K partials ----
#pragma unroll
    for (int mt = 0; mt < 2; mt++)
#pragma unroll
        for (int nb = 0; nb < 8; nb++) {
            int gr = r0 + wm * 32 + mt * 16 + (lane >> 2);
            int cl = c0 + wn * 64 + nb * 8 + (lane & 3) * 2;
            float* base = &g_part[((size_t)kh * NV + gr) * DV + cl];
            *(float2*)base            = make_float2(acc[mt][nb][0], acc[mt][nb][1]);
            *(float2*)(base + 8 * DV) = make_float2(acc[mt][nb][2], acc[mt][nb][3]);
        }
}

// ---------------------------------------------------------------------------
// Kernel 5: combine split-K partials + elu
// ---------------------------------------------------------------------------
__global__ __launch_bounds__(256) void k_combine(float* __restrict__ out_elu) {
    float* o = out_elu ? out_elu : g_elu_scratch;
    size_t i = ((size_t)blockIdx.x * 256 + threadIdx.x) * 4;
    float4 p0 = *(float4*)&g_part[i];
    float4 p1 = *(float4*)&g_part[(size_t)NV * DV + i];
    float4 r;
    r.x = elu_f(p0.x + p1.x);
    r.y = elu_f(p0.y + p1.y);
    r.z = elu_f(p0.z + p1.z);
    r.w = elu_f(p0.w + p1.w);
    *(float4*)&o[i] = r;
}

// ---------------------------------------------------------------------------
extern "C" void kernel_launch(void* const* d_in, const int* in_sizes, int n_in,
                              void* d_out, int out_size) {
    const float* h   = (const float*)d_in[0];
    const int*   adj = (const int*)d_in[1];
    const float* W   = (const float*)d_in[2];
    const float* a   = (const float*)d_in[3];
    float* out = (float*)d_out;

    const long long elu_n = (long long)NV * DV;
    const long long alp_n = (long long)NV * NV;
    float* out_elu;
    float* out_alpha;
    if ((long long)out_size >= elu_n + alp_n) { out_elu = out; out_alpha = out + elu_n; }
    else if ((long long)out_size == alp_n)    { out_elu = nullptr; out_alpha = out; }
    else                                      { out_elu = out; out_alpha = nullptr; }

    cudaFuncSetAttribute(k_wh_mma, cudaFuncAttributeMaxDynamicSharedMemorySize, WH_SMEM);
    cudaFuncSetAttribute(k_attn,   cudaFuncAttributeMaxDynamicSharedMemorySize, AT_SMEM);

    dim3 gW(NV / 128, 2);
    k_wh_mma<<<gW, 512, WH_SMEM>>>(h, W, a);
    k_f<<<NV / 8, 256>>>(h);
    k_prep<<<NV, 256>>>(adj);
    dim3 gA(4, NV / 128);
    k_attn<<<gA, 256, AT_SMEM>>>(out_alpha);
    k_combine<<<(unsigned)(elu_n / 4 / 256), 256>>>(out_elu);
}

// round 13
// speedup vs baseline: 1.8400x; 1.4384x over previous
#include <cuda_runtime.h>
#include <cuda_fp16.h>
#include <cstdint>
#include <math.h>

#define NV 8192
#define DV 256

// ---------------- device scratch (allocation-free rule) ----------------
__device__ __half   g_WhT16[DV * NV];   // Wh^T, fp16, [col][j] (B operand)
__device__ float    g_wa[DV];           // W @ a
__device__ float    g_u[NV];            // exp(f)
__device__ float    g_v[NV];            // exp(0.2 f)
__device__ float    g_c[NV];            // u/s
__device__ float    g_d[NV];            // v/s
__device__ unsigned g_bm[NV * 256];     // adjacency bitmask
__device__ float    g_part[2 * NV * DV];
__device__ float    g_elu_scratch[NV * DV];

__device__ __forceinline__ float elu_f(float x) { return x > 0.f ? x : expm1f(x); }
__device__ __forceinline__ uint32_t tf32r(float x) {
    uint32_t r; asm("cvt.rna.tf32.f32 %0, %1;" : "=r"(r) : "f"(x)); return r;
}
// tf32 k8 mma (used by k_wh_mma)
__device__ __forceinline__ void mma_tf32(float* d, const uint32_t* a, const uint32_t* b) {
    asm volatile("mma.sync.aligned.m16n8k8.row.col.f32.tf32.tf32.f32 "
        "{%0,%1,%2,%3},{%4,%5,%6,%7},{%8,%9},{%0,%1,%2,%3};"
        : "+f"(d[0]), "+f"(d[1]), "+f"(d[2]), "+f"(d[3])
        : "r"(a[0]), "r"(a[1]), "r"(a[2]), "r"(a[3]), "r"(b[0]), "r"(b[1]));
}
// fp16 k16 mma (k_attn)
__device__ __forceinline__ void mma_f16(float* d, const uint32_t* a, const uint32_t* b) {
    asm volatile("mma.sync.aligned.m16n8k16.row.col.f32.f16.f16.f32 "
        "{%0,%1,%2,%3},{%4,%5,%6,%7},{%8,%9},{%0,%1,%2,%3};"
        : "+f"(d[0]), "+f"(d[1]), "+f"(d[2]), "+f"(d[3])
        : "r"(a[0]), "r"(a[1]), "r"(a[2]), "r"(a[3]), "r"(b[0]), "r"(b[1]));
}
__device__ __forceinline__ uint32_t smem_u32(const void* p) {
    uint32_t a;
    asm("{ .reg .u64 t; cvta.to.shared.u64 t, %1; cvt.u32.u64 %0, t; }" : "=r"(a) : "l"(p));
    return a;
}
__device__ __forceinline__ void cp_async16(uint32_t dst, const void* src) {
    asm volatile("cp.async.ca.shared.global [%0], [%1], 16;" :: "r"(dst), "l"(src));
}
#define CP_COMMIT() asm volatile("cp.async.commit_group;" ::: "memory")
#define CP_WAIT1()  asm volatile("cp.async.wait_group 1;" ::: "memory")
__device__ __forceinline__ uint32_t h2pack(float lo, float hi) {
    __half2 h = __floats2half2_rn(lo, hi);          // .x -> low 16 bits
    return *reinterpret_cast<uint32_t*>(&h);
}

// ---------------------------------------------------------------------------
// Kernel 1: Wh = h @ W via tf32 mma; epilogue writes fp16 Wh^T [col][j].
// Also computes wa = W@a in block (0,0). CTA = 128 x 128 (grid 64x2).
// ---------------------------------------------------------------------------
#define WH_SMEM (128 * 36 * 4 + 32 * 136 * 4)
__global__ __launch_bounds__(512) void k_wh_mma(const float* __restrict__ h,
                                                const float* __restrict__ W,
                                                const float* __restrict__ a) {
    extern __shared__ char sm[];
    uint32_t* sA = (uint32_t*)sm;
    float*    sB = (float*)(sm + 128 * 36 * 4);
    const int tid = threadIdx.x;
    const int wid = tid >> 5, lane = tid & 31;
    const int wm = wid >> 2, wn = wid & 3;
    const int r0 = blockIdx.x * 128;
    const int cb = blockIdx.y * 128;
    const int br = tid >> 2, kq = (tid & 3) * 8;

    if (blockIdx.x == 0 && blockIdx.y == 0 && tid < 256) {
        const float4* W4 = (const float4*)W;
        const float4* a4 = (const float4*)a;
        float s = 0.f;
#pragma unroll 8
        for (int j = 0; j < 64; j++) {
            float4 w = __ldg(&W4[tid * 64 + j]);
            float4 av = __ldg(&a4[j]);
            s += w.x * av.x + w.y * av.y + w.z * av.z + w.w * av.w;
        }
        g_wa[tid] = s;
    }

    float acc[2][4][4];
#pragma unroll
    for (int mt = 0; mt < 2; mt++)
#pragma unroll
        for (int nb = 0; nb < 4; nb++)
#pragma unroll
            for (int q = 0; q < 4; q++) acc[mt][nb][q] = 0.f;

    for (int c = 0; c < 8; c++) {
        const int kb = c * 32;
        {
            float4 h0 = __ldg((const float4*)&h[(size_t)(r0 + br) * DV + kb + kq]);
            float4 h1 = __ldg((const float4*)&h[(size_t)(r0 + br) * DV + kb + kq + 4]);
            *(uint4*)&sA[br * 36 + kq]     = make_uint4(tf32r(h0.x), tf32r(h0.y), tf32r(h0.z), tf32r(h0.w));
            *(uint4*)&sA[br * 36 + kq + 4] = make_uint4(tf32r(h1.x), tf32r(h1.y), tf32r(h1.z), tf32r(h1.w));
        }
#pragma unroll
        for (int q = 0; q < 2; q++) {
            int idx = q * 512 + tid;
            int row = idx >> 5, col = (idx & 31) << 2;
            float4 w = __ldg((const float4*)&W[(size_t)(kb + row) * DV + cb + col]);
            float4 t;
            t.x = __uint_as_float(tf32r(w.x)); t.y = __uint_as_float(tf32r(w.y));
            t.z = __uint_as_float(tf32r(w.z)); t.w = __uint_as_float(tf32r(w.w));
            *(float4*)&sB[row * 136 + col] = t;
        }
        __syncthreads();
#pragma unroll
        for (int kk = 0; kk < 4; kk++) {
            uint32_t afr[2][4];
#pragma unroll
            for (int mt = 0; mt < 2; mt++) {
                int r = wm * 32 + mt * 16 + (lane >> 2);
                int cc = kk * 8 + (lane & 3);
                afr[mt][0] = sA[r * 36 + cc];
                afr[mt][1] = sA[(r + 8) * 36 + cc];
                afr[mt][2] = sA[r * 36 + cc + 4];
                afr[mt][3] = sA[(r + 8) * 36 + cc + 4];
            }
#pragma unroll
            for (int nb = 0; nb < 4; nb++) {
                uint32_t bfr[2];
                int kr = kk * 8 + (lane & 3);
                int nc = wn * 32 + nb * 8 + (lane >> 2);
                bfr[0] = __float_as_uint(sB[kr * 136 + nc]);
                bfr[1] = __float_as_uint(sB[(kr + 4) * 136 + nc]);
                mma_tf32(acc[0][nb], afr[0], bfr);
                mma_tf32(acc[1][nb], afr[1], bfr);
            }
        }
        __syncthreads();
    }
    // epilogue: fp16 Wh^T [col][j]
#pragma unroll
    for (int mt = 0; mt < 2; mt++)
#pragma unroll
        for (int nb = 0; nb < 4; nb++) {
            int gr = r0 + wm * 32 + mt * 16 + (lane >> 2);
            int cl = cb + wn * 32 + nb * 8 + (lane & 3) * 2;
            g_WhT16[(size_t)cl * NV + gr]           = __float2half_rn(acc[mt][nb][0]);
            g_WhT16[(size_t)(cl + 1) * NV + gr]     = __float2half_rn(acc[mt][nb][1]);
            g_WhT16[(size_t)cl * NV + gr + 8]       = __float2half_rn(acc[mt][nb][2]);
            g_WhT16[(size_t)(cl + 1) * NV + gr + 8] = __float2half_rn(acc[mt][nb][3]);
        }
}

// ---------------------------------------------------------------------------
// Kernel 2: f = h @ wa (exact); u = exp(f), v = exp(0.2 f)
// ---------------------------------------------------------------------------
__global__ __launch_bounds__(256) void k_f(const float* __restrict__ h) {
    const int wid = threadIdx.x >> 5, lane = threadIdx.x & 31;
    const int row = blockIdx.x * 8 + wid;
    float s = 0.f;
#pragma unroll
    for (int i = 0; i < 2; i++) {
        float4 w = __ldg((const float4*)&h[(size_t)row * DV + lane * 8 + i * 4]);
        float4 av = __ldg((const float4*)&g_wa[lane * 8 + i * 4]);
        s += w.x * av.x + w.y * av.y + w.z * av.z + w.w * av.w;
    }
#pragma unroll
    for (int m = 16; m; m >>= 1) s += __shfl_xor_sync(0xffffffffu, s, m);
    if (lane == 0) {
        g_u[row] = __expf(s);
        g_v[row] = __expf(0.2f * s);
    }
}

// ---------------------------------------------------------------------------
// Kernel 3: bitmask + rowsum (separable). One block per row.
// ---------------------------------------------------------------------------
__global__ __launch_bounds__(256) void k_prep(const int* __restrict__ adj) {
    const int row = blockIdx.x;
    const int wid = threadIdx.x >> 5, lane = threadIdx.x & 31;
    const float ui = __ldg(&g_u[row]);
    const float vi = __ldg(&g_v[row]);
    const float th = 1.f / ui;
    const int4* ar = (const int4*)(adj + (size_t)row * NV);
    const float4* u4p = (const float4*)g_u;
    const float4* v4p = (const float4*)g_v;

    float su = 0.f, sv = 0.f;
#pragma unroll
    for (int it = 0; it < 8; it++) {
        int idx4 = wid * 256 + it * 32 + lane;
        int4   ad = __ldg(&ar[idx4]);
        float4 u4 = __ldg(&u4p[idx4]);
        float4 v4 = __ldg(&v4p[idx4]);
        bool m0 = ad.x > 0, m1 = ad.y > 0, m2 = ad.z > 0, m3 = ad.w > 0;
        uint32_t nib = (m0 ? 1u : 0u) | (m1 ? 2u : 0u) | (m2 ? 4u : 0u) | (m3 ? 8u : 0u);
        bool p0 = u4.x > th, p1 = u4.y > th, p2 = u4.z > th, p3 = u4.w > th;
        su += (m0 && p0) ? u4.x : 0.f;  sv += (m0 && !p0) ? v4.x : 0.f;
        su += (m1 && p1) ? u4.y : 0.f;  sv += (m1 && !p1) ? v4.y : 0.f;
        su += (m2 && p2) ? u4.z : 0.f;  sv += (m2 && !p2) ? v4.z : 0.f;
        su += (m3 && p3) ? u4.w : 0.f;  sv += (m3 && !p3) ? v4.w : 0.f;
        uint32_t o = __shfl_xor_sync(0xffffffffu, nib, 1);
        uint32_t byt = (lane & 1) ? (o | (nib << 4)) : (nib | (o << 4));
        o = __shfl_xor_sync(0xffffffffu, byt, 2);
        uint32_t hlf = (lane & 2) ? (o | (byt << 8)) : (byt | (o << 8));
        o = __shfl_xor_sync(0xffffffffu, hlf, 4);
        uint32_t wrd = (lane & 4) ? (o | (hlf << 16)) : (hlf | (o << 16));
        if ((lane & 7) == 0)
            g_bm[(size_t)row * 256 + wid * 32 + it * 4 + (lane >> 3)] = wrd;
    }
#pragma unroll
    for (int m = 16; m; m >>= 1) {
        su += __shfl_xor_sync(0xffffffffu, su, m);
        sv += __shfl_xor_sync(0xffffffffu, sv, m);
    }
    __shared__ float ssu[8], ssv[8];
    if (lane == 0) { ssu[wid] = su; ssv[wid] = sv; }
    __syncthreads();
    if (threadIdx.x == 0) {
        float tu = 0.f, tv = 0.f;
#pragma unroll
        for (int i = 0; i < 8; i++) { tu += ssu[i]; tv += ssv[i]; }
        float s = ui * tu + vi * tv;
        g_c[row] = ui / s;
        g_d[row] = vi / s;
    }
}

// ---------------------------------------------------------------------------
// Kernel 4: h' = alpha @ Wh via fp16 m16n8k16 mma. 512 threads, 16 warps
// (4x4), warp tile 32x64, CTA 128 x 256, split-K=2 (128 CTAs, one wave).
// u/v in SMEM; B: fp16 3-stage cp.async ring (pitch-20 rows, conflict-free);
// A: fp16-pair fragment rows (pitch 20), built in SMEM; bm prefetch 2 ahead.
// ---------------------------------------------------------------------------
#define AT_U   0
#define AT_V   (AT_U + NV * 4)                 // 32 KB each
#define AT_A   (AT_V + NV * 4)                 // 2 x 128*20*4 = 20480
#define AT_B   (AT_A + 2 * 10240)              // 3 x 256*20*4 = 61440
#define AT_SC  (AT_B + 3 * 20480)
#define AT_SMEM (AT_SC + 3 * 128 * 4)          // 148992 B

__global__ __launch_bounds__(512, 1) void k_attn(float* __restrict__ out_alpha) {
    extern __shared__ char sm[];
    float*    sU = (float*)(sm + AT_U);
    float*    sV = (float*)(sm + AT_V);
    uint32_t* sAs[2] = { (uint32_t*)(sm + AT_A), (uint32_t*)(sm + AT_A + 10240) };
    float* sc  = (float*)(sm + AT_SC);
    float* sd  = sc + 128;
    float* stt = sd + 128;

    const int tid = threadIdx.x;
    const int wid = tid >> 5, lane = tid & 31;
    const int wm = wid >> 2, wn = wid & 3;        // 4 x 4 warps, tile 32x64
    const int kh = blockIdx.x, rt = blockIdx.y;
    const int r0 = rt * 128;
    const int br = tid >> 2, kq0 = (tid & 3) * 8; // A-build: 8 els/thread
    const bool wA = (out_alpha != nullptr);
    const uint32_t sbB = smem_u32(sm + AT_B);
    const size_t bmBase = (size_t)(r0 + br) * 256 + (size_t)kh * 128;

    // preload u, v, row constants
#pragma unroll
    for (int q = 0; q < 4; q++) {
        int idx = (q * 512 + tid) * 4;
        *(float4*)&sU[idx] = *(const float4*)&g_u[idx];
        *(float4*)&sV[idx] = *(const float4*)&g_v[idx];
    }
    if (tid < 128) {
        sc[tid]  = g_c[r0 + tid];
        sd[tid]  = g_d[r0 + tid];
        stt[tid] = 1.f / g_u[r0 + tid];
    }

    float acc[2][8][4];
#pragma unroll
    for (int mt = 0; mt < 2; mt++)
#pragma unroll
        for (int nb = 0; nb < 8; nb++)
#pragma unroll
            for (int q = 0; q < 4; q++) acc[mt][nb][q] = 0.f;
    __syncthreads();

    // B tile: fp16 Wh^T rows [n][k-pairs], pitch 20 words (16 used)
    auto cp_B = [&](int c, int s) {
        const int kb = kh * (NV / 2) + c * 32;
        uint32_t base = sbB + s * 20480;
#pragma unroll
        for (int q = 0; q < 2; q++) {
            int idx = q * 512 + tid;
            int n = idx >> 2, seg = idx & 3;      // seg: 8 fp16 (16B)
            cp_async16(base + (n * 20 + seg * 4) * 4,
                       (const char*)g_WhT16 + ((size_t)n * NV + kb + seg * 8) * 2);
        }
    };
    auto build_A = [&](int c, int s, uint32_t word) {
        const int kb = kh * (NV / 2) + c * 32;
        float ci = sc[br], di = sd[br], th = stt[br];
        float4 u0 = *(const float4*)&sU[kb + kq0];
        float4 u1 = *(const float4*)&sU[kb + kq0 + 4];
        float4 v0 = *(const float4*)&sV[kb + kq0];
        float4 v1 = *(const float4*)&sV[kb + kq0 + 4];
        const float ue[8] = {u0.x, u0.y, u0.z, u0.w, u1.x, u1.y, u1.z, u1.w};
        const float ve[8] = {v0.x, v0.y, v0.z, v0.w, v1.x, v1.y, v1.z, v1.w};
        float av[8];
#pragma unroll
        for (int e = 0; e < 8; e++) {
            bool bit = (word >> (kq0 + e)) & 1u;
            av[e] = bit ? ((ue[e] > th) ? ci * ue[e] : di * ve[e]) : 0.f;
        }
        if (wA) {
            float* dst = &out_alpha[(size_t)(r0 + br) * NV + kb + kq0];
            *(float4*)dst       = make_float4(av[0], av[1], av[2], av[3]);
            *(float4*)(dst + 4) = make_float4(av[4], av[5], av[6], av[7]);
        }
        uint4 pw = make_uint4(h2pack(av[0], av[1]), h2pack(av[2], av[3]),
                              h2pack(av[4], av[5]), h2pack(av[6], av[7]));
        *(uint4*)&sAs[s][br * 20 + (kq0 >> 1)] = pw;
    };
    auto do_mma = [&](int sa, int sb) {
        uint32_t* sA = sAs[sa];
        const uint32_t* sB = (const uint32_t*)(sm + AT_B + sb * 20480);
#pragma unroll
        for (int kk = 0; kk < 2; kk++) {
            uint32_t afr[2][4];
#pragma unroll
            for (int mt = 0; mt < 2; mt++) {
                int r = wm * 32 + mt * 16 + (lane >> 2);
                int cc = kk * 8 + (lane & 3);
                afr[mt][0] = sA[r * 20 + cc];
                afr[mt][1] = sA[(r + 8) * 20 + cc];
                afr[mt][2] = sA[r * 20 + cc + 4];
                afr[mt][3] = sA[(r + 8) * 20 + cc + 4];
            }
            int kp = kk * 8 + (lane & 3);
#pragma unroll
            for (int nb = 0; nb < 8; nb++) {
                int n = wn * 64 + nb * 8 + (lane >> 2);
                uint32_t bfr[2];
                bfr[0] = sB[n * 20 + kp];
                bfr[1] = sB[n * 20 + kp + 4];
                mma_f16(acc[0][nb], afr[0], bfr);
                mma_f16(acc[1][nb], afr[1], bfr);
            }
        }
    };

    // ---- prologue: B stages 0,1 in flight; A(0) built; bm prefetched ----
    uint32_t wcur = __ldg(&g_bm[bmBase + 0]);
    cp_B(0, 0); CP_COMMIT();
    cp_B(1, 1); CP_COMMIT();
    build_A(0, 0, wcur);
    wcur = __ldg(&g_bm[bmBase + 1]);
    CP_WAIT1();                                   // B(0) retired
    __syncthreads();

#pragma unroll 1
    for (int c = 0; c < 128; c++) {
        uint32_t wpre = 0;
        if (c + 2 < 128) wpre = __ldg(&g_bm[bmBase + c + 2]);
        do_mma(c & 1, c % 3);
        if (c + 2 < 128) cp_B(c + 2, (c + 2) % 3);
        CP_COMMIT();
        if (c < 127) build_A(c + 1, (c + 1) & 1, wcur);
        wcur = wpre;
        CP_WAIT1();                               // B(c+1) retired before barrier
        __syncthreads();
    }

    // ---- epilogue: split-K partials ----
#pragma unroll
    for (int mt = 0; mt < 2; mt++)
#pragma unroll
        for (int nb = 0; nb < 8; nb++) {
            int gr = r0 + wm * 32 + mt * 16 + (lane >> 2);
            int cl = wn * 64 + nb * 8 + (lane & 3) * 2;
            float* base = &g_part[((size_t)kh * NV + gr) * DV + cl];
            *(float2*)base            = make_float2(acc[mt][nb][0], acc[mt][nb][1]);
            *(float2*)(base + 8 * DV) = make_float2(acc[mt][nb][2], acc[mt][nb][3]);
        }
}

// ---------------------------------------------------------------------------
// Kernel 5: combine split-K partials + elu
// ---------------------------------------------------------------------------
__global__ __launch_bounds__(256) void k_combine(float* __restrict__ out_elu) {
    float* o = out_elu ? out_elu : g_elu_scratch;
    size_t i = ((size_t)blockIdx.x * 256 + threadIdx.x) * 4;
    float4 p0 = *(float4*)&g_part[i];
    float4 p1 = *(float4*)&g_part[(size_t)NV * DV + i];
    float4 r;
    r.x = elu_f(p0.x + p1.x);
    r.y = elu_f(p0.y + p1.y);
    r.z = elu_f(p0.z + p1.z);
    r.w = elu_f(p0.w + p1.w);
    *(float4*)&o[i] = r;
}

// ---------------------------------------------------------------------------
extern "C" void kernel_launch(void* const* d_in, const int* in_sizes, int n_in,
                              void* d_out, int out_size) {
    const float* h   = (const float*)d_in[0];
    const int*   adj = (const int*)d_in[1];
    const float* W   = (const float*)d_in[2];
    const float* a   = (const float*)d_in[3];
    float* out = (float*)d_out;

    const long long elu_n = (long long)NV * DV;
    const long long alp_n = (long long)NV * NV;
    float* out_elu;
    float* out_alpha;
    if ((long long)out_size >= elu_n + alp_n) { out_elu = out; out_alpha = out + elu_n; }
    else if ((long long)out_size == alp_n)    { out_elu = nullptr; out_alpha = out; }
    else                                      { out_elu = out; out_alpha = nullptr; }

    cudaFuncSetAttribute(k_wh_mma, cudaFuncAttributeMaxDynamicSharedMemorySize, WH_SMEM);
    cudaFuncSetAttribute(k_attn,   cudaFuncAttributeMaxDynamicSharedMemorySize, AT_SMEM);

    dim3 gW(NV / 128, 2);
    k_wh_mma<<<gW, 512, WH_SMEM>>>(h, W, a);
    k_f<<<NV / 8, 256>>>(h);
    k_prep<<<NV, 256>>>(adj);
    dim3 gA(2, NV / 128);
    k_attn<<<gA, 512, AT_SMEM>>>(out_alpha);
    k_combine<<<(unsigned)(elu_n / 4 / 256), 256>>>(out_elu);
}

// round 15
// speedup vs baseline: 1.9638x; 1.0673x over previous
#include <cuda_runtime.h>
#include <cuda_fp16.h>
#include <cstdint>
#include <math.h>

#define NV 8192
#define DV 256

// ---------------- device scratch (allocation-free rule) ----------------
__device__ __half   g_WhT16[DV * NV];   // Wh^T, fp16, [col][j] (B operand)
__device__ float    g_wa[DV];           // W @ a
__device__ float    g_u[NV];            // exp(f)
__device__ float    g_v[NV];            // exp(0.2 f)
__device__ float    g_c[NV];            // u/s
__device__ float    g_d[NV];            // v/s
__device__ unsigned g_bm[NV * 256];     // adjacency bitmask
__device__ float    g_part[2 * NV * DV];
__device__ float    g_elu_scratch[NV * DV];

__device__ __forceinline__ float elu_f(float x) { return x > 0.f ? x : expm1f(x); }
__device__ __forceinline__ uint32_t tf32r(float x) {
    uint32_t r; asm("cvt.rna.tf32.f32 %0, %1;" : "=r"(r) : "f"(x)); return r;
}
__device__ __forceinline__ void mma_tf32(float* d, const uint32_t* a, const uint32_t* b) {
    asm volatile("mma.sync.aligned.m16n8k8.row.col.f32.tf32.tf32.f32 "
        "{%0,%1,%2,%3},{%4,%5,%6,%7},{%8,%9},{%0,%1,%2,%3};"
        : "+f"(d[0]), "+f"(d[1]), "+f"(d[2]), "+f"(d[3])
        : "r"(a[0]), "r"(a[1]), "r"(a[2]), "r"(a[3]), "r"(b[0]), "r"(b[1]));
}
__device__ __forceinline__ void mma_f16(float* d, const uint32_t* a, const uint32_t* b) {
    asm volatile("mma.sync.aligned.m16n8k16.row.col.f32.f16.f16.f32 "
        "{%0,%1,%2,%3},{%4,%5,%6,%7},{%8,%9},{%0,%1,%2,%3};"
        : "+f"(d[0]), "+f"(d[1]), "+f"(d[2]), "+f"(d[3])
        : "r"(a[0]), "r"(a[1]), "r"(a[2]), "r"(a[3]), "r"(b[0]), "r"(b[1]));
}
__device__ __forceinline__ uint32_t smem_u32(const void* p) {
    uint32_t a;
    asm("{ .reg .u64 t; cvta.to.shared.u64 t, %1; cvt.u32.u64 %0, t; }" : "=r"(a) : "l"(p));
    return a;
}
__device__ __forceinline__ void cp_async16(uint32_t dst, const void* src) {
    asm volatile("cp.async.ca.shared.global [%0], [%1], 16;" :: "r"(dst), "l"(src));
}
#define CP_COMMIT() asm volatile("cp.async.commit_group;" ::: "memory")
#define CP_WAIT0()  asm volatile("cp.async.wait_group 0;" ::: "memory")
__device__ __forceinline__ uint32_t h2pack(float lo, float hi) {
    __half2 h = __floats2half2_rn(lo, hi);
    return *reinterpret_cast<uint32_t*>(&h);
}

// ---------------------------------------------------------------------------
// Kernel 1: Wh = h @ W via tf32 mma; epilogue writes fp16 Wh^T [col][j].
// Also computes wa = W@a in block (0,0). CTA = 128 x 128 (grid 64x2).
// ---------------------------------------------------------------------------
#define WH_SMEM (128 * 36 * 4 + 32 * 136 * 4)
__global__ __launch_bounds__(512) void k_wh_mma(const float* __restrict__ h,
                                                const float* __restrict__ W,
                                                const float* __restrict__ a) {
    extern __shared__ char sm[];
    uint32_t* sA = (uint32_t*)sm;
    float*    sB = (float*)(sm + 128 * 36 * 4);
    const int tid = threadIdx.x;
    const int wid = tid >> 5, lane = tid & 31;
    const int wm = wid >> 2, wn = wid & 3;
    const int r0 = blockIdx.x * 128;
    const int cb = blockIdx.y * 128;
    const int br = tid >> 2, kq = (tid & 3) * 8;

    if (blockIdx.x == 0 && blockIdx.y == 0 && tid < 256) {
        const float4* W4 = (const float4*)W;
        const float4* a4 = (const float4*)a;
        float s = 0.f;
#pragma unroll 8
        for (int j = 0; j < 64; j++) {
            float4 w = __ldg(&W4[tid * 64 + j]);
            float4 av = __ldg(&a4[j]);
            s += w.x * av.x + w.y * av.y + w.z * av.z + w.w * av.w;
        }
        g_wa[tid] = s;
    }

    float acc[2][4][4];
#pragma unroll
    for (int mt = 0; mt < 2; mt++)
#pragma unroll
        for (int nb = 0; nb < 4; nb++)
#pragma unroll
            for (int q = 0; q < 4; q++) acc[mt][nb][q] = 0.f;

    for (int c = 0; c < 8; c++) {
        const int kb = c * 32;
        {
            float4 h0 = __ldg((const float4*)&h[(size_t)(r0 + br) * DV + kb + kq]);
            float4 h1 = __ldg((const float4*)&h[(size_t)(r0 + br) * DV + kb + kq + 4]);
            *(uint4*)&sA[br * 36 + kq]     = make_uint4(tf32r(h0.x), tf32r(h0.y), tf32r(h0.z), tf32r(h0.w));
            *(uint4*)&sA[br * 36 + kq + 4] = make_uint4(tf32r(h1.x), tf32r(h1.y), tf32r(h1.z), tf32r(h1.w));
        }
#pragma unroll
        for (int q = 0; q < 2; q++) {
            int idx = q * 512 + tid;
            int row = idx >> 5, col = (idx & 31) << 2;
            float4 w = __ldg((const float4*)&W[(size_t)(kb + row) * DV + cb + col]);
            float4 t;
            t.x = __uint_as_float(tf32r(w.x)); t.y = __uint_as_float(tf32r(w.y));
            t.z = __uint_as_float(tf32r(w.z)); t.w = __uint_as_float(tf32r(w.w));
            *(float4*)&sB[row * 136 + col] = t;
        }
        __syncthreads();
#pragma unroll
        for (int kk = 0; kk < 4; kk++) {
            uint32_t afr[2][4];
#pragma unroll
            for (int mt = 0; mt < 2; mt++) {
                int r = wm * 32 + mt * 16 + (lane >> 2);
                int cc = kk * 8 + (lane & 3);
                afr[mt][0] = sA[r * 36 + cc];
                afr[mt][1] = sA[(r + 8) * 36 + cc];
                afr[mt][2] = sA[r * 36 + cc + 4];
                afr[mt][3] = sA[(r + 8) * 36 + cc + 4];
            }
#pragma unroll
            for (int nb = 0; nb < 4; nb++) {
                uint32_t bfr[2];
                int kr = kk * 8 + (lane & 3);
                int nc = wn * 32 + nb * 8 + (lane >> 2);
                bfr[0] = __float_as_uint(sB[kr * 136 + nc]);
                bfr[1] = __float_as_uint(sB[(kr + 4) * 136 + nc]);
                mma_tf32(acc[0][nb], afr[0], bfr);
                mma_tf32(acc[1][nb], afr[1], bfr);
            }
        }
        __syncthreads();
    }
#pragma unroll
    for (int mt = 0; mt < 2; mt++)
#pragma unroll
        for (int nb = 0; nb < 4; nb++) {
            int gr = r0 + wm * 32 + mt * 16 + (lane >> 2);
            int cl = cb + wn * 32 + nb * 8 + (lane & 3) * 2;
            g_WhT16[(size_t)cl * NV + gr]           = __float2half_rn(acc[mt][nb][0]);
            g_WhT16[(size_t)(cl + 1) * NV + gr]     = __float2half_rn(acc[mt][nb][1]);
            g_WhT16[(size_t)cl * NV + gr + 8]       = __float2half_rn(acc[mt][nb][2]);
            g_WhT16[(size_t)(cl + 1) * NV + gr + 8] = __float2half_rn(acc[mt][nb][3]);
        }
}

// ---------------------------------------------------------------------------
// Kernel 2: f = h @ wa (exact); u = exp(f), v = exp(0.2 f)
// ---------------------------------------------------------------------------
__global__ __launch_bounds__(256) void k_f(const float* __restrict__ h) {
    const int wid = threadIdx.x >> 5, lane = threadIdx.x & 31;
    const int row = blockIdx.x * 8 + wid;
    float s = 0.f;
#pragma unroll
    for (int i = 0; i < 2; i++) {
        float4 w = __ldg((const float4*)&h[(size_t)row * DV + lane * 8 + i * 4]);
        float4 av = __ldg((const float4*)&g_wa[lane * 8 + i * 4]);
        s += w.x * av.x + w.y * av.y + w.z * av.z + w.w * av.w;
    }
#pragma unroll
    for (int m = 16; m; m >>= 1) s += __shfl_xor_sync(0xffffffffu, s, m);
    if (lane == 0) {
        g_u[row] = __expf(s);
        g_v[row] = __expf(0.2f * s);
    }
}

// ---------------------------------------------------------------------------
// Kernel 3: bitmask + rowsum (separable). One block per row.
// ---------------------------------------------------------------------------
__global__ __launch_bounds__(256) void k_prep(const int* __restrict__ adj) {
    const int row = blockIdx.x;
    const int wid = threadIdx.x >> 5, lane = threadIdx.x & 31;
    const float ui = __ldg(&g_u[row]);
    const float vi = __ldg(&g_v[row]);
    const float th = 1.f / ui;
    const int4* ar = (const int4*)(adj + (size_t)row * NV);
    const float4* u4p = (const float4*)g_u;
    const float4* v4p = (const float4*)g_v;

    float su = 0.f, sv = 0.f;
#pragma unroll
    for (int it = 0; it < 8; it++) {
        int idx4 = wid * 256 + it * 32 + lane;
        int4   ad = __ldg(&ar[idx4]);
        float4 u4 = __ldg(&u4p[idx4]);
        float4 v4 = __ldg(&v4p[idx4]);
        bool m0 = ad.x > 0, m1 = ad.y > 0, m2 = ad.z > 0, m3 = ad.w > 0;
        uint32_t nib = (m0 ? 1u : 0u) | (m1 ? 2u : 0u) | (m2 ? 4u : 0u) | (m3 ? 8u : 0u);
        bool p0 = u4.x > th, p1 = u4.y > th, p2 = u4.z > th, p3 = u4.w > th;
        su += (m0 && p0) ? u4.x : 0.f;  sv += (m0 && !p0) ? v4.x : 0.f;
        su += (m1 && p1) ? u4.y : 0.f;  sv += (m1 && !p1) ? v4.y : 0.f;
        su += (m2 && p2) ? u4.z : 0.f;  sv += (m2 && !p2) ? v4.z : 0.f;
        su += (m3 && p3) ? u4.w : 0.f;  sv += (m3 && !p3) ? v4.w : 0.f;
        uint32_t o = __shfl_xor_sync(0xffffffffu, nib, 1);
        uint32_t byt = (lane & 1) ? (o | (nib << 4)) : (nib | (o << 4));
        o = __shfl_xor_sync(0xffffffffu, byt, 2);
        uint32_t hlf = (lane & 2) ? (o | (byt << 8)) : (byt | (o << 8));
        o = __shfl_xor_sync(0xffffffffu, hlf, 4);
        uint32_t wrd = (lane & 4) ? (o | (hlf << 16)) : (hlf | (o << 16));
        if ((lane & 7) == 0)
            g_bm[(size_t)row * 256 + wid * 32 + it * 4 + (lane >> 3)] = wrd;
    }
#pragma unroll
    for (int m = 16; m; m >>= 1) {
        su += __shfl_xor_sync(0xffffffffu, su, m);
        sv += __shfl_xor_sync(0xffffffffu, sv, m);
    }
    __shared__ float ssu[8], ssv[8];
    if (lane == 0) { ssu[wid] = su; ssv[wid] = sv; }
    __syncthreads();
    if (threadIdx.x == 0) {
        float tu = 0.f, tv = 0.f;
#pragma unroll
        for (int i = 0; i < 8; i++) { tu += ssu[i]; tv += ssv[i]; }
        float s = ui * tu + vi * tv;
        g_c[row] = ui / s;
        g_d[row] = vi / s;
    }
}

// ---------------------------------------------------------------------------
// Kernel 4: h' = alpha @ Wh via fp16 m16n8k16. K-step 64 per barrier
// (8 k16 MMA steps/iter, 64 iters). 512 threads, 16 warps (4x4), warp tile
// 32x64, CTA 128 x 256, split-K=2. A/B double-buffered; cp_B issued for
// stage (it+1)&1 BEFORE do_mma(it&1) -> no stage collision with 2 buffers.
// ---------------------------------------------------------------------------
#define AT_U   0
#define AT_V   (AT_U + NV * 4)                 // 32 KB each
#define AT_A   (AT_V + NV * 4)                 // 2 x 128*36*4 = 36864
#define AT_B   (AT_A + 2 * 18432)              // 2 x 256*36*4 = 73728
#define AT_SC  (AT_B + 2 * 36864)
#define AT_SMEM (AT_SC + 3 * 128 * 4)          // 178688 B

__global__ __launch_bounds__(512, 1) void k_attn(float* __restrict__ out_alpha) {
    extern __shared__ char sm[];
    float*    sU = (float*)(sm + AT_U);
    float*    sV = (float*)(sm + AT_V);
    uint32_t* sAs[2] = { (uint32_t*)(sm + AT_A), (uint32_t*)(sm + AT_A + 18432) };
    float* sc  = (float*)(sm + AT_SC);
    float* sd  = sc + 128;
    float* stt = sd + 128;

    const int tid = threadIdx.x;
    const int wid = tid >> 5, lane = tid & 31;
    const int wm = wid >> 2, wn = wid & 3;        // 4 x 4 warps, tile 32x64
    const int kh = blockIdx.x, rt = blockIdx.y;
    const int r0 = rt * 128;
    const int br = tid >> 2, kq0 = (tid & 3) * 16; // A-build: 16 els/thread
    const bool wA = (out_alpha != nullptr);
    const uint32_t sbB = smem_u32(sm + AT_B);
    const unsigned* bmPtr = &g_bm[(size_t)(r0 + br) * 256 + (size_t)kh * 128];

    // preload u, v, row constants
#pragma unroll
    for (int q = 0; q < 4; q++) {
        int idx = (q * 512 + tid) * 4;
        *(float4*)&sU[idx] = *(const float4*)&g_u[idx];
        *(float4*)&sV[idx] = *(const float4*)&g_v[idx];
    }
    if (tid < 128) {
        sc[tid]  = g_c[r0 + tid];
        sd[tid]  = g_d[r0 + tid];
        stt[tid] = 1.f / g_u[r0 + tid];
    }

    float acc[2][8][4];
#pragma unroll
    for (int mt = 0; mt < 2; mt++)
#pragma unroll
        for (int nb = 0; nb < 8; nb++)
#pragma unroll
            for (int q = 0; q < 4; q++) acc[mt][nb][q] = 0.f;
    __syncthreads();

    // B tile: 256 n-rows x 32 k-pair words, pitch 36
    auto cp_B = [&](int it, int s) {
        const int kb = kh * (NV / 2) + it * 64;
        uint32_t base = sbB + s * 36864;
#pragma unroll
        for (int q = 0; q < 4; q++) {
            int idx = q * 512 + tid;
            int n = idx >> 3, seg = idx & 7;      // seg: 8 fp16 (16B)
            cp_async16(base + (n * 36 + seg * 4) * 4,
                       (const char*)g_WhT16 + ((size_t)n * NV + kb + seg * 8) * 2);
        }
    };
    // A tile: 128 rows x 32 k-pair words, pitch 36. 16 alphas/thread.
    auto build_A = [&](int it, int s, uint2 w2) {
        const int kb = kh * (NV / 2) + it * 64;
        float ci = sc[br], di = sd[br], th = stt[br];
        uint32_t word = ((tid & 3) < 2) ? w2.x : w2.y;
        int sh = kq0 & 16;                        // bit base within word
        uint32_t* sA = sAs[s];
#pragma unroll
        for (int hf = 0; hf < 2; hf++) {          // two halves of 8
            int j = kq0 + hf * 8;
            float4 u0 = *(const float4*)&sU[kb + j];
            float4 u1 = *(const float4*)&sU[kb + j + 4];
            float4 v0 = *(const float4*)&sV[kb + j];
            float4 v1 = *(const float4*)&sV[kb + j + 4];
            const float ue[8] = {u0.x, u0.y, u0.z, u0.w, u1.x, u1.y, u1.z, u1.w};
            const float ve[8] = {v0.x, v0.y, v0.z, v0.w, v1.x, v1.y, v1.z, v1.w};
            float av[8];
#pragma unroll
            for (int e = 0; e < 8; e++) {
                bool bit = (word >> (sh + hf * 8 + e)) & 1u;
                av[e] = bit ? ((ue[e] > th) ? ci * ue[e] : di * ve[e]) : 0.f;
            }
            if (wA) {
                float* dst = &out_alpha[(size_t)(r0 + br) * NV + kb + j];
                *(float4*)dst       = make_float4(av[0], av[1], av[2], av[3]);
                *(float4*)(dst + 4) = make_float4(av[4], av[5], av[6], av[7]);
            }
            uint4 pw = make_uint4(h2pack(av[0], av[1]), h2pack(av[2], av[3]),
                                  h2pack(av[4], av[5]), h2pack(av[6], av[7]));
            *(uint4*)&sA[br * 36 + (j >> 1)] = pw;
        }
    };
    auto do_mma = [&](int s) {
        uint32_t* sA = sAs[s];
        const uint32_t* sB = (const uint32_t*)(sm + AT_B + s * 36864);
#pragma unroll
        for (int kk = 0; kk < 4; kk++) {
            uint32_t afr[2][4];
#pragma unroll
            for (int mt = 0; mt < 2; mt++) {
                int r = wm * 32 + mt * 16 + (lane >> 2);
                int cc = kk * 8 + (lane & 3);
                afr[mt][0] = sA[r * 36 + cc];
                afr[mt][1] = sA[(r + 8) * 36 + cc];
                afr[mt][2] = sA[r * 36 + cc + 4];
                afr[mt][3] = sA[(r + 8) * 36 + cc + 4];
            }
            int kp = kk * 8 + (lane & 3);
#pragma unroll
            for (int nb = 0; nb < 8; nb++) {
                int n = wn * 64 + nb * 8 + (lane >> 2);
                uint32_t bfr[2];
                bfr[0] = sB[n * 36 + kp];
                bfr[1] = sB[n * 36 + kp + 4];
                mma_f16(acc[0][nb], afr[0], bfr);
                mma_f16(acc[1][nb], afr[1], bfr);
            }
        }
    };

    // ---- prologue: B(0) in flight; A(0) built; bm for it=1 prefetched ----
    uint2 wcur = *(const uint2*)&bmPtr[0];
    cp_B(0, 0); CP_COMMIT();
    build_A(0, 0, wcur);
    wcur = *(const uint2*)&bmPtr[2];
    CP_WAIT0();                                   // B(0) resident
    __syncthreads();

#pragma unroll 1
    for (int it = 0; it < 64; it++) {
        uint2 wpre = make_uint2(0, 0);
        if (it + 2 < 64) wpre = *(const uint2*)&bmPtr[(it + 2) * 2];
        if (it + 1 < 64) cp_B(it + 1, (it + 1) & 1);   // stage not in use this iter
        CP_COMMIT();
        do_mma(it & 1);
        if (it < 63) build_A(it + 1, (it + 1) & 1, wcur);
        wcur = wpre;
        CP_WAIT0();                               // B(it+1) resident before barrier
        __syncthreads();
    }

    // ---- epilogue: split-K partials ----
#pragma unroll
    for (int mt = 0; mt < 2; mt++)
#pragma unroll
        for (int nb = 0; nb < 8; nb++) {
            int gr = r0 + wm * 32 + mt * 16 + (lane >> 2);
            int cl = wn * 64 + nb * 8 + (lane & 3) * 2;
            float* base = &g_part[((size_t)kh * NV + gr) * DV + cl];
            *(float2*)base            = make_float2(acc[mt][nb][0], acc[mt][nb][1]);
            *(float2*)(base + 8 * DV) = make_float2(acc[mt][nb][2], acc[mt][nb][3]);
        }
}

// ---------------------------------------------------------------------------
// Kernel 5: combine split-K partials + elu
// ---------------------------------------------------------------------------
__global__ __launch_bounds__(256) void k_combine(float* __restrict__ out_elu) {
    float* o = out_elu ? out_elu : g_elu_scratch;
    size_t i = ((size_t)blockIdx.x * 256 + threadIdx.x) * 4;
    float4 p0 = *(float4*)&g_part[i];
    float4 p1 = *(float4*)&g_part[(size_t)NV * DV + i];
    float4 r;
    r.x = elu_f(p0.x + p1.x);
    r.y = elu_f(p0.y + p1.y);
    r.z = elu_f(p0.z + p1.z);
    r.w = elu_f(p0.w + p1.w);
    *(float4*)&o[i] = r;
}

// ---------------------------------------------------------------------------
extern "C" void kernel_launch(void* const* d_in, const int* in_sizes, int n_in,
                              void* d_out, int out_size) {
    const float* h   = (const float*)d_in[0];
    const int*   adj = (const int*)d_in[1];
    const float* W   = (const float*)d_in[2];
    const float* a   = (const float*)d_in[3];
    float* out = (float*)d_out;

    const long long elu_n = (long long)NV * DV;
    const long long alp_n = (long long)NV * NV;
    float* out_elu;
    float* out_alpha;
    if ((long long)out_size >= elu_n + alp_n) { out_elu = out; out_alpha = out + elu_n; }
    else if ((long long)out_size == alp_n)    { out_elu = nullptr; out_alpha = out; }
    else                                      { out_elu = out; out_alpha = nullptr; }

    cudaFuncSetAttribute(k_wh_mma, cudaFuncAttributeMaxDynamicSharedMemorySize, WH_SMEM);
    cudaFuncSetAttribute(k_attn,   cudaFuncAttributeMaxDynamicSharedMemorySize, AT_SMEM);

    dim3 gW(NV / 128, 2);
    k_wh_mma<<<gW, 512, WH_SMEM>>>(h, W, a);
    k_f<<<NV / 8, 256>>>(h);
    k_prep<<<NV, 256>>>(adj);
    dim3 gA(2, NV / 128);
    k_attn<<<gA, 512, AT_SMEM>>>(out_alpha);
    k_combine<<<(unsigned)(elu_n / 4 / 256), 256>>>(out_elu);
}